// round 1
// baseline (speedup 1.0000x reference)
#include <cuda_runtime.h>
#include <math.h>

#define D_MODEL   1024
#define NUM_HEADS 16
#define HEAD_DIM  64
#define BATCH     4
#define SEQ       2048
#define M_TOT     (BATCH * SEQ)   // 8192

// ---------------- scratch (allocation-free rule: __device__ globals) ----------
__device__ float g_Q[(size_t)M_TOT * D_MODEL];
__device__ float g_K[(size_t)M_TOT * D_MODEL];
__device__ float g_V[(size_t)M_TOT * D_MODEL];
__device__ float g_C[(size_t)M_TOT * D_MODEL];

// ---------------- SGEMM: C[M,N] = A[M,K] @ B[K,N] + bias ----------------------
#define GBM 128
#define GBN 64
#define GBK 16
#define GTM 8
#define GTN 4

__global__ __launch_bounds__(256) void sgemm_bias(
    const float* __restrict__ A, const float* __restrict__ Bm,
    const float* __restrict__ bias, float* __restrict__ C,
    int M, int N, int K)
{
    __shared__ float As[GBK][GBM + 4];   // stride 132 floats = 528B (16B aligned)
    __shared__ float Bs[GBK][GBN + 4];   // stride 68  floats = 272B (16B aligned)

    const int tid  = threadIdx.x;
    const int tx   = tid & 15;   // 0..15 col group
    const int ty   = tid >> 4;   // 0..15 row group
    const int row0 = blockIdx.y * GBM;
    const int col0 = blockIdx.x * GBN;

    float acc[GTM][GTN];
#pragma unroll
    for (int i = 0; i < GTM; i++)
#pragma unroll
        for (int j = 0; j < GTN; j++) acc[i][j] = 0.f;

    for (int k0 = 0; k0 < K; k0 += GBK) {
        // A tile: GBM x GBK = 2048 floats = 512 float4, 2 per thread (transposed store)
#pragma unroll
        for (int ld = 0; ld < 2; ld++) {
            int idx = tid + ld * 256;            // 0..511
            int r   = idx >> 2;                  // 0..127
            int kq  = (idx & 3) << 2;            // 0,4,8,12
            float4 v = *(const float4*)&A[(size_t)(row0 + r) * K + k0 + kq];
            As[kq + 0][r] = v.x;
            As[kq + 1][r] = v.y;
            As[kq + 2][r] = v.z;
            As[kq + 3][r] = v.w;
        }
        // B tile: GBK x GBN = 1024 floats = 256 float4, 1 per thread
        {
            int kk = tid >> 4;                   // 0..15
            int cq = (tid & 15) << 2;            // 0..60
            float4 v = *(const float4*)&Bm[(size_t)(k0 + kk) * N + col0 + cq];
            *(float4*)&Bs[kk][cq] = v;
        }
        __syncthreads();

#pragma unroll
        for (int kk = 0; kk < GBK; kk++) {
            float4 a0 = *(const float4*)&As[kk][ty * GTM];
            float4 a1 = *(const float4*)&As[kk][ty * GTM + 4];
            float4 b0 = *(const float4*)&Bs[kk][tx * GTN];
            float av[GTM] = {a0.x, a0.y, a0.z, a0.w, a1.x, a1.y, a1.z, a1.w};
            float bv[GTN] = {b0.x, b0.y, b0.z, b0.w};
#pragma unroll
            for (int i = 0; i < GTM; i++)
#pragma unroll
                for (int j = 0; j < GTN; j++)
                    acc[i][j] += av[i] * bv[j];
        }
        __syncthreads();
    }

#pragma unroll
    for (int i = 0; i < GTM; i++) {
        int r = row0 + ty * GTM + i;
        int c = col0 + tx * GTN;
        float4 o;
        o.x = acc[i][0] + bias[c + 0];
        o.y = acc[i][1] + bias[c + 1];
        o.z = acc[i][2] + bias[c + 2];
        o.w = acc[i][3] + bias[c + 3];
        *(float4*)&C[(size_t)r * N + c] = o;
    }
}

// ---------------- RoPE (in place on projected Q and K) ------------------------
__global__ void rope_kernel(float* __restrict__ Q, float* __restrict__ K)
{
    int idx = blockIdx.x * blockDim.x + threadIdx.x;
    if (idx >= M_TOT * NUM_HEADS * (HEAD_DIM / 2)) return;
    int j   = idx & 31;                   // rotary pair index 0..31
    int h   = (idx >> 5) & (NUM_HEADS - 1);
    int row = idx >> 9;                   // b*SEQ + t, 0..8191
    int t   = row & (SEQ - 1);

    // inv_freq = 10000^(-j/32); double so it rounds to the exact fp32 value
    double e = exp(-(double)j * (9.210340371976184 / 32.0));
    float ang = (float)t * (float)e;
    float c = cosf(ang), s = sinf(ang);

    size_t base = (size_t)row * D_MODEL + h * HEAD_DIM + j;
    float q1 = Q[base], q2 = Q[base + 32];
    Q[base]      = q1 * c - q2 * s;
    Q[base + 32] = q2 * c + q1 * s;
    float k1 = K[base], k2 = K[base + 32];
    K[base]      = k1 * c - k2 * s;
    K[base + 32] = k2 * c + k1 * s;
}

// ---------------- Flash attention, fp32, Br=Bc=64 -----------------------------
#define QT_STRIDE 68   // float4-aligned rows (272B), broadcast-friendly
#define PT_STRIDE 65   // odd stride: conflict-light scalar transposed access

__global__ __launch_bounds__(256) void flash_attn(
    const float* __restrict__ Qp, const float* __restrict__ Kp,
    const float* __restrict__ Vp, float* __restrict__ Cp)
{
    extern __shared__ float smem[];
    float (*Qt)[QT_STRIDE] = (float (*)[QT_STRIDE])(smem);                   // [d][r]
    float (*Kt)[QT_STRIDE] = (float (*)[QT_STRIDE])(smem + 64 * QT_STRIDE); // [d][c]
    float (*Vs)[QT_STRIDE] = (float (*)[QT_STRIDE])(smem + 2 * 64 * QT_STRIDE); // [s][dc]
    float (*Pt)[PT_STRIDE] = (float (*)[PT_STRIDE])(smem + 3 * 64 * QT_STRIDE); // [s][r]

    const int tid = threadIdx.x;
    const int tx  = tid & 15;     // 0..15 -> 4 score-cols / 4 d-cols
    const int ty  = tid >> 4;     // 0..15 -> 4 query rows
    const int q0  = blockIdx.x * 64;
    const int h   = blockIdx.y;
    const int b   = blockIdx.z;
    const size_t basebh = (size_t)b * SEQ * D_MODEL + (size_t)h * HEAD_DIM;

    // Load Q tile transposed, pre-scaled by 1/sqrt(hd) = 0.125
#pragma unroll
    for (int ld = 0; ld < 4; ld++) {
        int idx = tid + ld * 256;
        int r   = idx >> 4;
        int dq  = (idx & 15) << 2;
        float4 v = *(const float4*)&Qp[basebh + (size_t)(q0 + r) * D_MODEL + dq];
        Qt[dq + 0][r] = v.x * 0.125f;
        Qt[dq + 1][r] = v.y * 0.125f;
        Qt[dq + 2][r] = v.z * 0.125f;
        Qt[dq + 3][r] = v.w * 0.125f;
    }

    float m_i[4], l_i[4], O[4][4];
#pragma unroll
    for (int i = 0; i < 4; i++) {
        m_i[i] = -1e30f;
        l_i[i] = 0.f;
#pragma unroll
        for (int j = 0; j < 4; j++) O[i][j] = 0.f;
    }

    for (int s0 = 0; s0 < SEQ; s0 += 64) {
        __syncthreads();   // prior iteration's PV (Pt/Vs readers) done; Qt visible on iter 0
        // Load K transposed + V natural
#pragma unroll
        for (int ld = 0; ld < 4; ld++) {
            int idx = tid + ld * 256;
            int c   = idx >> 4;
            int dq  = (idx & 15) << 2;
            size_t g = basebh + (size_t)(s0 + c) * D_MODEL + dq;
            float4 kv = *(const float4*)&Kp[g];
            Kt[dq + 0][c] = kv.x;
            Kt[dq + 1][c] = kv.y;
            Kt[dq + 2][c] = kv.z;
            Kt[dq + 3][c] = kv.w;
            float4 vv = *(const float4*)&Vp[g];
            *(float4*)&Vs[c][dq] = vv;
        }
        __syncthreads();

        // S = (Q/8) K^T  — 4x4 per thread, outer product over d
        float sacc[4][4];
#pragma unroll
        for (int i = 0; i < 4; i++)
#pragma unroll
            for (int j = 0; j < 4; j++) sacc[i][j] = 0.f;

#pragma unroll 8
        for (int d = 0; d < 64; d++) {
            float4 a  = *(const float4*)&Qt[d][ty << 2];
            float4 bb = *(const float4*)&Kt[d][tx << 2];
            float av[4] = {a.x, a.y, a.z, a.w};
            float bv[4] = {bb.x, bb.y, bb.z, bb.w};
#pragma unroll
            for (int i = 0; i < 4; i++)
#pragma unroll
                for (int j = 0; j < 4; j++)
                    sacc[i][j] += av[i] * bv[j];
        }

        // online softmax (row groups = 16 consecutive lanes sharing ty)
#pragma unroll
        for (int i = 0; i < 4; i++) {
            float mx = fmaxf(fmaxf(sacc[i][0], sacc[i][1]), fmaxf(sacc[i][2], sacc[i][3]));
#pragma unroll
            for (int off = 8; off >= 1; off >>= 1)
                mx = fmaxf(mx, __shfl_xor_sync(0xffffffffu, mx, off));
            float mn    = fmaxf(m_i[i], mx);
            float alpha = __expf(m_i[i] - mn);
            m_i[i] = mn;
            float su = 0.f;
#pragma unroll
            for (int j = 0; j < 4; j++) {
                float p = __expf(sacc[i][j] - mn);
                sacc[i][j] = p;
                su += p;
            }
#pragma unroll
            for (int off = 8; off >= 1; off >>= 1)
                su += __shfl_xor_sync(0xffffffffu, su, off);
            l_i[i] = l_i[i] * alpha + su;
#pragma unroll
            for (int j = 0; j < 4; j++) O[i][j] *= alpha;
        }

        // store P transposed: Pt[s][r]
#pragma unroll
        for (int j = 0; j < 4; j++)
#pragma unroll
            for (int i = 0; i < 4; i++)
                Pt[(tx << 2) + j][(ty << 2) + i] = sacc[i][j];
        __syncthreads();

        // O += P V  — outer product over s; Pt reads broadcast, Vs float4
#pragma unroll 8
        for (int s = 0; s < 64; s++) {
            float av[4];
            av[0] = Pt[s][(ty << 2) + 0];
            av[1] = Pt[s][(ty << 2) + 1];
            av[2] = Pt[s][(ty << 2) + 2];
            av[3] = Pt[s][(ty << 2) + 3];
            float4 b4 = *(const float4*)&Vs[s][tx << 2];
            float bv[4] = {b4.x, b4.y, b4.z, b4.w};
#pragma unroll
            for (int i = 0; i < 4; i++)
#pragma unroll
                for (int j = 0; j < 4; j++)
                    O[i][j] += av[i] * bv[j];
        }
    }

    // normalize + write context in [b, t, h*64+d] layout
#pragma unroll
    for (int i = 0; i < 4; i++) {
        float inv = 1.0f / l_i[i];
        float4 o;
        o.x = O[i][0] * inv;
        o.y = O[i][1] * inv;
        o.z = O[i][2] * inv;
        o.w = O[i][3] * inv;
        size_t g = basebh + (size_t)(q0 + (ty << 2) + i) * D_MODEL + (tx << 2);
        *(float4*)&Cp[g] = o;
    }
}

// ---------------- launch --------------------------------------------------------
extern "C" void kernel_launch(void* const* d_in, const int* in_sizes, int n_in,
                              void* d_out, int out_size)
{
    const float* query = (const float*)d_in[0];
    const float* key   = (const float*)d_in[1];
    const float* value = (const float*)d_in[2];
    const float* Wq = (const float*)d_in[3];
    const float* bq = (const float*)d_in[4];
    const float* Wk = (const float*)d_in[5];
    const float* bk = (const float*)d_in[6];
    const float* Wv = (const float*)d_in[7];
    const float* bv = (const float*)d_in[8];
    const float* Wo = (const float*)d_in[9];
    const float* bo = (const float*)d_in[10];
    float* out = (float*)d_out;
    (void)in_sizes; (void)n_in; (void)out_size;

    float *gQ, *gK, *gV, *gC;
    cudaGetSymbolAddress((void**)&gQ, g_Q);
    cudaGetSymbolAddress((void**)&gK, g_K);
    cudaGetSymbolAddress((void**)&gV, g_V);
    cudaGetSymbolAddress((void**)&gC, g_C);

    dim3 ggrid(D_MODEL / GBN, M_TOT / GBM);   // (16, 64)
    sgemm_bias<<<ggrid, 256>>>(query, Wq, bq, gQ, M_TOT, D_MODEL, D_MODEL);
    sgemm_bias<<<ggrid, 256>>>(key,   Wk, bk, gK, M_TOT, D_MODEL, D_MODEL);
    sgemm_bias<<<ggrid, 256>>>(value, Wv, bv, gV, M_TOT, D_MODEL, D_MODEL);

    int nrope = M_TOT * NUM_HEADS * (HEAD_DIM / 2);
    rope_kernel<<<(nrope + 255) / 256, 256>>>(gQ, gK);

    int smem_bytes = (3 * 64 * QT_STRIDE + 64 * PT_STRIDE) * (int)sizeof(float); // 68,864 B
    cudaFuncSetAttribute(flash_attn, cudaFuncAttributeMaxDynamicSharedMemorySize, smem_bytes);
    flash_attn<<<dim3(SEQ / 64, NUM_HEADS, BATCH), 256, smem_bytes>>>(gQ, gK, gV, gC);

    sgemm_bias<<<ggrid, 256>>>(gC, Wo, bo, out, M_TOT, D_MODEL, D_MODEL);
}

// round 3
// speedup vs baseline: 1.3381x; 1.3381x over previous
#include <cuda_runtime.h>
#include <cuda_bf16.h>
#include <math.h>
#include <stdint.h>

#define D_MODEL   1024
#define NUM_HEADS 16
#define HEAD_DIM  64
#define BATCH     4
#define SEQ       2048
#define M_TOT     (BATCH * SEQ)   // 8192

// ---------------- scratch (allocation-free rule: __device__ globals) ----------
__device__ float g_Q[(size_t)M_TOT * D_MODEL];
__device__ float g_K[(size_t)M_TOT * D_MODEL];
__device__ float g_V[(size_t)M_TOT * D_MODEL];
__device__ float g_C[(size_t)M_TOT * D_MODEL];
__device__ __nv_bfloat16 g_Ah[(size_t)M_TOT * D_MODEL];
__device__ __nv_bfloat16 g_Al[(size_t)M_TOT * D_MODEL];
__device__ __nv_bfloat16 g_Bh[(size_t)D_MODEL * D_MODEL];
__device__ __nv_bfloat16 g_Bl[(size_t)D_MODEL * D_MODEL];
__device__ float g_cos[SEQ * 32];
__device__ float g_sin[SEQ * 32];

// ================= helpers =================
__device__ __forceinline__ uint32_t smem_u32(const void* p) {
    uint32_t a;
    asm("{ .reg .u64 t; cvta.to.shared.u64 t, %1; cvt.u32.u64 %0, t; }"
        : "=r"(a) : "l"(p));
    return a;
}
__device__ __forceinline__ void cp_async16(uint32_t saddr, const void* gaddr) {
    asm volatile("cp.async.cg.shared.global [%0], [%1], 16;" :: "r"(saddr), "l"(gaddr));
}
__device__ __forceinline__ void cp_commit() {
    asm volatile("cp.async.commit_group;");
}
template <int N>
__device__ __forceinline__ void cp_wait() {
    asm volatile("cp.async.wait_group %0;" :: "n"(N));
}
__device__ __forceinline__ void ldsm_x4(uint32_t* d, uint32_t saddr) {
    asm volatile("ldmatrix.sync.aligned.m8n8.x4.shared.b16 {%0,%1,%2,%3}, [%4];"
        : "=r"(d[0]), "=r"(d[1]), "=r"(d[2]), "=r"(d[3]) : "r"(saddr));
}
__device__ __forceinline__ void mma_bf16(float* c, const uint32_t* a, const uint32_t* b) {
    asm volatile(
        "mma.sync.aligned.m16n8k16.row.col.f32.bf16.bf16.f32 "
        "{%0,%1,%2,%3}, {%4,%5,%6,%7}, {%8,%9}, {%0,%1,%2,%3};"
        : "+f"(c[0]), "+f"(c[1]), "+f"(c[2]), "+f"(c[3])
        : "r"(a[0]), "r"(a[1]), "r"(a[2]), "r"(a[3]), "r"(b[0]), "r"(b[1]));
}

// ============== bf16 split conversions ==============
__global__ void split_bf16(const float4* __restrict__ x,
                           __nv_bfloat162* __restrict__ hi,
                           __nv_bfloat162* __restrict__ lo, int n4)
{
    int i = blockIdx.x * blockDim.x + threadIdx.x;
    if (i >= n4) return;
    float4 v = x[i];
    __nv_bfloat16 h0 = __float2bfloat16_rn(v.x);
    __nv_bfloat16 h1 = __float2bfloat16_rn(v.y);
    __nv_bfloat16 h2 = __float2bfloat16_rn(v.z);
    __nv_bfloat16 h3 = __float2bfloat16_rn(v.w);
    __nv_bfloat16 l0 = __float2bfloat16_rn(v.x - __bfloat162float(h0));
    __nv_bfloat16 l1 = __float2bfloat16_rn(v.y - __bfloat162float(h1));
    __nv_bfloat16 l2 = __float2bfloat16_rn(v.z - __bfloat162float(h2));
    __nv_bfloat16 l3 = __float2bfloat16_rn(v.w - __bfloat162float(h3));
    hi[2 * i + 0] = __nv_bfloat162(h0, h1);
    hi[2 * i + 1] = __nv_bfloat162(h2, h3);
    lo[2 * i + 0] = __nv_bfloat162(l0, l1);
    lo[2 * i + 1] = __nv_bfloat162(l2, l3);
}

// W[K][N] fp32 -> hi/lo[N][K] bf16 (transpose + split)
__global__ void splitT_bf16(const float* __restrict__ W,
                            __nv_bfloat16* __restrict__ hi,
                            __nv_bfloat16* __restrict__ lo)
{
    __shared__ float t[32][33];
    int n0 = blockIdx.x * 32, k0 = blockIdx.y * 32;
    int tx = threadIdx.x, ty = threadIdx.y;  // (32, 8)
#pragma unroll
    for (int r = 0; r < 4; r++)
        t[ty + 8 * r][tx] = W[(size_t)(k0 + ty + 8 * r) * D_MODEL + n0 + tx];
    __syncthreads();
#pragma unroll
    for (int r = 0; r < 4; r++) {
        float v = t[tx][ty + 8 * r];
        __nv_bfloat16 h = __float2bfloat16_rn(v);
        __nv_bfloat16 l = __float2bfloat16_rn(v - __bfloat162float(h));
        size_t o = (size_t)(n0 + ty + 8 * r) * D_MODEL + k0 + tx;
        hi[o] = h;
        lo[o] = l;
    }
}

// ============== mma.sync bf16-split GEMM: C[M,N] = A @ Bt^T + bias ============
// A hi/lo: [M,K] bf16 row-major; Bt hi/lo: [N,K] bf16 row-major
#define TBM 128
#define TBN 128
#define TBK 32
#define LDE   40                  // padded row stride (elements)
#define ROWB  (LDE * 2)           // 80 bytes
#define TILE_B  (TBM * ROWB)      // 10240 B per tile
#define STAGE_B (4 * TILE_B)      // 40960 B per stage (Ah, Al, Bh, Bl)
#define GEMM_SMEM (2 * STAGE_B)   // 81920 B
#define KCH (D_MODEL / TBK)       // 32 chunks

__global__ __launch_bounds__(256) void gemm_bf16split(
    const __nv_bfloat16* __restrict__ Ah, const __nv_bfloat16* __restrict__ Al,
    const __nv_bfloat16* __restrict__ Bh, const __nv_bfloat16* __restrict__ Bl,
    const float* __restrict__ bias, float* __restrict__ C)
{
    extern __shared__ char smem[];
    const uint32_t sbase = smem_u32(smem);
    const int tid  = threadIdx.x;
    const int wid  = tid >> 5;
    const int lane = tid & 31;
    const int row0 = blockIdx.y * TBM;
    const int col0 = blockIdx.x * TBN;
    const int K = D_MODEL, N = D_MODEL;

    const int wr = (wid >> 1) * 32;   // warp row base in tile
    const int wc = (wid & 1) * 64;    // warp col base in tile

    // per-thread load slots: 2 uint4 per tile per chunk
    const int r_ld  = tid >> 2;          // 0..63  (+64 on second slot)
    const int c_ld  = (tid & 3) * 16;    // byte col within 64B row
    const int c_el  = (tid & 3) * 8;     // element col

    float acc[2][8][4];
#pragma unroll
    for (int mi = 0; mi < 2; mi++)
#pragma unroll
        for (int ni = 0; ni < 8; ni++)
#pragma unroll
            for (int q = 0; q < 4; q++) acc[mi][ni][q] = 0.f;

    // ---- async load of one chunk into stage s ----
    auto load_chunk = [&](int kc, int s) {
        uint32_t st = sbase + s * STAGE_B;
#pragma unroll
        for (int t = 0; t < 2; t++) {
            int r = r_ld + t * 64;
            uint32_t so = r * ROWB + c_ld;
            size_t ga = (size_t)(row0 + r) * K + kc + c_el;
            size_t gb = (size_t)(col0 + r) * K + kc + c_el;
            cp_async16(st + 0 * TILE_B + so, Ah + ga);
            cp_async16(st + 1 * TILE_B + so, Al + ga);
            cp_async16(st + 2 * TILE_B + so, Bh + gb);
            cp_async16(st + 3 * TILE_B + so, Bl + gb);
        }
        cp_commit();
    };

    load_chunk(0, 0);

    for (int i = 0; i < KCH; i++) {
        if (i + 1 < KCH) {
            load_chunk((i + 1) * TBK, (i + 1) & 1);
            cp_wait<1>();
        } else {
            cp_wait<0>();
        }
        __syncthreads();

        const uint32_t st = sbase + (i & 1) * STAGE_B;

#pragma unroll
        for (int k16 = 0; k16 < 2; k16++) {
            const int ko = k16 * 16;
            // A fragments (hi & lo) for both m16 rows
            uint32_t ah[2][4], al[2][4];
#pragma unroll
            for (int mi = 0; mi < 2; mi++) {
                uint32_t ao = (uint32_t)(wr + mi * 16 + (lane & 15)) * ROWB
                            + (uint32_t)(ko + ((lane >> 4) << 3)) * 2;
                ldsm_x4(ah[mi], st + 0 * TILE_B + ao);
                ldsm_x4(al[mi], st + 1 * TILE_B + ao);
            }
            // B fragments: 4 pairs of n8 tiles
#pragma unroll
            for (int np = 0; np < 4; np++) {
                uint32_t bo = (uint32_t)(wc + np * 16 + ((lane >> 4) << 3) + (lane & 7)) * ROWB
                            + (uint32_t)(ko + (((lane >> 3) & 1) << 3)) * 2;
                uint32_t bh[4], bl[4];
                ldsm_x4(bh, st + 2 * TILE_B + bo);
                ldsm_x4(bl, st + 3 * TILE_B + bo);
#pragma unroll
                for (int mi = 0; mi < 2; mi++) {
                    mma_bf16(acc[mi][2 * np + 0], ah[mi], bh + 0);
                    mma_bf16(acc[mi][2 * np + 1], ah[mi], bh + 2);
                    mma_bf16(acc[mi][2 * np + 0], ah[mi], bl + 0);
                    mma_bf16(acc[mi][2 * np + 1], ah[mi], bl + 2);
                    mma_bf16(acc[mi][2 * np + 0], al[mi], bh + 0);
                    mma_bf16(acc[mi][2 * np + 1], al[mi], bh + 2);
                }
            }
        }
        __syncthreads();
    }

    // ---- epilogue: bias + store fp32 ----
    const int r_in = lane >> 2;
    const int c_in = (lane & 3) * 2;
#pragma unroll
    for (int mi = 0; mi < 2; mi++) {
#pragma unroll
        for (int ni = 0; ni < 8; ni++) {
            int col = col0 + wc + ni * 8 + c_in;
            float b0 = bias[col], b1 = bias[col + 1];
            int row = row0 + wr + mi * 16 + r_in;
            float2 o0 = make_float2(acc[mi][ni][0] + b0, acc[mi][ni][1] + b1);
            float2 o1 = make_float2(acc[mi][ni][2] + b0, acc[mi][ni][3] + b1);
            *(float2*)&C[(size_t)row * N + col] = o0;
            *(float2*)&C[(size_t)(row + 8) * N + col] = o1;
        }
    }
}

// ---------------- RoPE table + apply ------------------------------------------
__global__ void rope_table_kernel()
{
    int idx = blockIdx.x * blockDim.x + threadIdx.x;
    if (idx >= SEQ * 32) return;
    int j = idx & 31;
    int t = idx >> 5;
    double e = exp(-(double)j * (9.210340371976184 / 32.0));  // 10000^(-j/32)
    float ang = (float)t * (float)e;
    g_cos[idx] = cosf(ang);
    g_sin[idx] = sinf(ang);
}

__global__ void rope_kernel(float* __restrict__ Q, float* __restrict__ K)
{
    int idx = blockIdx.x * blockDim.x + threadIdx.x;
    if (idx >= M_TOT * NUM_HEADS * (HEAD_DIM / 2)) return;
    int j   = idx & 31;
    int h   = (idx >> 5) & (NUM_HEADS - 1);
    int row = idx >> 9;
    int t   = row & (SEQ - 1);

    float c = g_cos[t * 32 + j];
    float s = g_sin[t * 32 + j];

    size_t base = (size_t)row * D_MODEL + h * HEAD_DIM + j;
    float q1 = Q[base], q2 = Q[base + 32];
    Q[base]      = q1 * c - q2 * s;
    Q[base + 32] = q2 * c + q1 * s;
    float k1 = K[base], k2 = K[base + 32];
    K[base]      = k1 * c - k2 * s;
    K[base + 32] = k2 * c + k1 * s;
}

// ---------------- Flash attention, fp32, Br=Bc=64 -----------------------------
#define QT_STRIDE 68
#define PT_STRIDE 65

__global__ __launch_bounds__(256) void flash_attn(
    const float* __restrict__ Qp, const float* __restrict__ Kp,
    const float* __restrict__ Vp, float* __restrict__ Cp)
{
    extern __shared__ float fsmem[];
    float (*Qt)[QT_STRIDE] = (float (*)[QT_STRIDE])(fsmem);
    float (*Kt)[QT_STRIDE] = (float (*)[QT_STRIDE])(fsmem + 64 * QT_STRIDE);
    float (*Vs)[QT_STRIDE] = (float (*)[QT_STRIDE])(fsmem + 2 * 64 * QT_STRIDE);
    float (*Pt)[PT_STRIDE] = (float (*)[PT_STRIDE])(fsmem + 3 * 64 * QT_STRIDE);

    const int tid = threadIdx.x;
    const int tx  = tid & 15;
    const int ty  = tid >> 4;
    const int q0  = blockIdx.x * 64;
    const int h   = blockIdx.y;
    const int b   = blockIdx.z;
    const size_t basebh = (size_t)b * SEQ * D_MODEL + (size_t)h * HEAD_DIM;

#pragma unroll
    for (int ld = 0; ld < 4; ld++) {
        int idx = tid + ld * 256;
        int r   = idx >> 4;
        int dq  = (idx & 15) << 2;
        float4 v = *(const float4*)&Qp[basebh + (size_t)(q0 + r) * D_MODEL + dq];
        Qt[dq + 0][r] = v.x * 0.125f;
        Qt[dq + 1][r] = v.y * 0.125f;
        Qt[dq + 2][r] = v.z * 0.125f;
        Qt[dq + 3][r] = v.w * 0.125f;
    }

    float m_i[4], l_i[4], O[4][4];
#pragma unroll
    for (int i = 0; i < 4; i++) {
        m_i[i] = -1e30f;
        l_i[i] = 0.f;
#pragma unroll
        for (int j = 0; j < 4; j++) O[i][j] = 0.f;
    }

    for (int s0 = 0; s0 < SEQ; s0 += 64) {
        __syncthreads();
#pragma unroll
        for (int ld = 0; ld < 4; ld++) {
            int idx = tid + ld * 256;
            int c   = idx >> 4;
            int dq  = (idx & 15) << 2;
            size_t g = basebh + (size_t)(s0 + c) * D_MODEL + dq;
            float4 kv = *(const float4*)&Kp[g];
            Kt[dq + 0][c] = kv.x;
            Kt[dq + 1][c] = kv.y;
            Kt[dq + 2][c] = kv.z;
            Kt[dq + 3][c] = kv.w;
            float4 vv = *(const float4*)&Vp[g];
            *(float4*)&Vs[c][dq] = vv;
        }
        __syncthreads();

        float sacc[4][4];
#pragma unroll
        for (int i = 0; i < 4; i++)
#pragma unroll
            for (int j = 0; j < 4; j++) sacc[i][j] = 0.f;

#pragma unroll 8
        for (int d = 0; d < 64; d++) {
            float4 a  = *(const float4*)&Qt[d][ty << 2];
            float4 bb = *(const float4*)&Kt[d][tx << 2];
            float av[4] = {a.x, a.y, a.z, a.w};
            float bv[4] = {bb.x, bb.y, bb.z, bb.w};
#pragma unroll
            for (int i = 0; i < 4; i++)
#pragma unroll
                for (int j = 0; j < 4; j++)
                    sacc[i][j] += av[i] * bv[j];
        }

#pragma unroll
        for (int i = 0; i < 4; i++) {
            float mx = fmaxf(fmaxf(sacc[i][0], sacc[i][1]), fmaxf(sacc[i][2], sacc[i][3]));
#pragma unroll
            for (int off = 8; off >= 1; off >>= 1)
                mx = fmaxf(mx, __shfl_xor_sync(0xffffffffu, mx, off));
            float mn    = fmaxf(m_i[i], mx);
            float alpha = __expf(m_i[i] - mn);
            m_i[i] = mn;
            float su = 0.f;
#pragma unroll
            for (int j = 0; j < 4; j++) {
                float p = __expf(sacc[i][j] - mn);
                sacc[i][j] = p;
                su += p;
            }
#pragma unroll
            for (int off = 8; off >= 1; off >>= 1)
                su += __shfl_xor_sync(0xffffffffu, su, off);
            l_i[i] = l_i[i] * alpha + su;
#pragma unroll
            for (int j = 0; j < 4; j++) O[i][j] *= alpha;
        }

#pragma unroll
        for (int j = 0; j < 4; j++)
#pragma unroll
            for (int i = 0; i < 4; i++)
                Pt[(tx << 2) + j][(ty << 2) + i] = sacc[i][j];
        __syncthreads();

#pragma unroll 8
        for (int s = 0; s < 64; s++) {
            float av[4];
            av[0] = Pt[s][(ty << 2) + 0];
            av[1] = Pt[s][(ty << 2) + 1];
            av[2] = Pt[s][(ty << 2) + 2];
            av[3] = Pt[s][(ty << 2) + 3];
            float4 b4 = *(const float4*)&Vs[s][tx << 2];
            float bv[4] = {b4.x, b4.y, b4.z, b4.w};
#pragma unroll
            for (int i = 0; i < 4; i++)
#pragma unroll
                for (int j = 0; j < 4; j++)
                    O[i][j] += av[i] * bv[j];
        }
    }

#pragma unroll
    for (int i = 0; i < 4; i++) {
        float inv = 1.0f / l_i[i];
        float4 o;
        o.x = O[i][0] * inv;
        o.y = O[i][1] * inv;
        o.z = O[i][2] * inv;
        o.w = O[i][3] * inv;
        size_t g = basebh + (size_t)(q0 + (ty << 2) + i) * D_MODEL + (tx << 2);
        *(float4*)&Cp[g] = o;
    }
}

// ---------------- launch --------------------------------------------------------
extern "C" void kernel_launch(void* const* d_in, const int* in_sizes, int n_in,
                              void* d_out, int out_size)
{
    const float* query = (const float*)d_in[0];
    const float* key   = (const float*)d_in[1];
    const float* value = (const float*)d_in[2];
    const float* Wq = (const float*)d_in[3];
    const float* bq = (const float*)d_in[4];
    const float* Wk = (const float*)d_in[5];
    const float* bk = (const float*)d_in[6];
    const float* Wv = (const float*)d_in[7];
    const float* bv = (const float*)d_in[8];
    const float* Wo = (const float*)d_in[9];
    const float* bo = (const float*)d_in[10];
    float* out = (float*)d_out;
    (void)in_sizes; (void)n_in; (void)out_size;

    float *gQ, *gK, *gV, *gC;
    __nv_bfloat16 *gAh, *gAl, *gBh, *gBl;
    cudaGetSymbolAddress((void**)&gQ, g_Q);
    cudaGetSymbolAddress((void**)&gK, g_K);
    cudaGetSymbolAddress((void**)&gV, g_V);
    cudaGetSymbolAddress((void**)&gC, g_C);
    cudaGetSymbolAddress((void**)&gAh, g_Ah);
    cudaGetSymbolAddress((void**)&gAl, g_Al);
    cudaGetSymbolAddress((void**)&gBh, g_Bh);
    cudaGetSymbolAddress((void**)&gBl, g_Bl);

    const int n4 = M_TOT * D_MODEL / 4;
    const dim3 tgrid(D_MODEL / 32, D_MODEL / 32);
    const dim3 tblk(32, 8);
    const dim3 ggrid(D_MODEL / TBN, M_TOT / TBM);   // (8, 64)

    cudaFuncSetAttribute(gemm_bf16split,
                         cudaFuncAttributeMaxDynamicSharedMemorySize, GEMM_SMEM);

    rope_table_kernel<<<(SEQ * 32 + 255) / 256, 256>>>();

    // Q projection
    split_bf16<<<(n4 + 255) / 256, 256>>>((const float4*)query,
        (__nv_bfloat162*)gAh, (__nv_bfloat162*)gAl, n4);
    splitT_bf16<<<tgrid, tblk>>>(Wq, gBh, gBl);
    gemm_bf16split<<<ggrid, 256, GEMM_SMEM>>>(gAh, gAl, gBh, gBl, bq, gQ);
    // K projection
    split_bf16<<<(n4 + 255) / 256, 256>>>((const float4*)key,
        (__nv_bfloat162*)gAh, (__nv_bfloat162*)gAl, n4);
    splitT_bf16<<<tgrid, tblk>>>(Wk, gBh, gBl);
    gemm_bf16split<<<ggrid, 256, GEMM_SMEM>>>(gAh, gAl, gBh, gBl, bk, gK);
    // V projection
    split_bf16<<<(n4 + 255) / 256, 256>>>((const float4*)value,
        (__nv_bfloat162*)gAh, (__nv_bfloat162*)gAl, n4);
    splitT_bf16<<<tgrid, tblk>>>(Wv, gBh, gBl);
    gemm_bf16split<<<ggrid, 256, GEMM_SMEM>>>(gAh, gAl, gBh, gBl, bv, gV);

    // RoPE
    int nrope = M_TOT * NUM_HEADS * (HEAD_DIM / 2);
    rope_kernel<<<(nrope + 255) / 256, 256>>>(gQ, gK);

    // attention
    int smem_bytes = (3 * 64 * QT_STRIDE + 64 * PT_STRIDE) * (int)sizeof(float);
    cudaFuncSetAttribute(flash_attn, cudaFuncAttributeMaxDynamicSharedMemorySize, smem_bytes);
    flash_attn<<<dim3(SEQ / 64, NUM_HEADS, BATCH), 256, smem_bytes>>>(gQ, gK, gV, gC);

    // output projection
    split_bf16<<<(n4 + 255) / 256, 256>>>((const float4*)gC,
        (__nv_bfloat162*)gAh, (__nv_bfloat162*)gAl, n4);
    splitT_bf16<<<tgrid, tblk>>>(Wo, gBh, gBl);
    gemm_bf16split<<<ggrid, 256, GEMM_SMEM>>>(gAh, gAl, gBh, gBl, bo, out);
}

// round 5
// speedup vs baseline: 2.6679x; 1.9938x over previous
#include <cuda_runtime.h>
#include <cuda_bf16.h>
#include <math.h>
#include <stdint.h>

#define D_MODEL   1024
#define NUM_HEADS 16
#define HEAD_DIM  64
#define BATCH     4
#define SEQ       2048
#define M_TOT     (BATCH * SEQ)   // 8192

// ---------------- scratch (allocation-free rule: __device__ globals) ----------
__device__ float g_Q[(size_t)M_TOT * D_MODEL];
__device__ float g_K[(size_t)M_TOT * D_MODEL];
__device__ float g_V[(size_t)M_TOT * D_MODEL];
__device__ float g_C[(size_t)M_TOT * D_MODEL];
__device__ __nv_bfloat16 g_Ah[(size_t)M_TOT * D_MODEL];
__device__ __nv_bfloat16 g_Al[(size_t)M_TOT * D_MODEL];
__device__ __nv_bfloat16 g_Bh[(size_t)D_MODEL * D_MODEL];
__device__ __nv_bfloat16 g_Bl[(size_t)D_MODEL * D_MODEL];
__device__ __nv_bfloat16 g_Qh[(size_t)M_TOT * D_MODEL];
__device__ __nv_bfloat16 g_Ql[(size_t)M_TOT * D_MODEL];
__device__ __nv_bfloat16 g_Kh[(size_t)M_TOT * D_MODEL];
__device__ __nv_bfloat16 g_Kl[(size_t)M_TOT * D_MODEL];
__device__ __nv_bfloat16 g_Vth[(size_t)M_TOT * D_MODEL];  // [b,h,d,s]
__device__ __nv_bfloat16 g_Vtl[(size_t)M_TOT * D_MODEL];
__device__ float g_cos[SEQ * 32];
__device__ float g_sin[SEQ * 32];

// ================= helpers =================
__device__ __forceinline__ uint32_t smem_u32(const void* p) {
    uint32_t a;
    asm("{ .reg .u64 t; cvta.to.shared.u64 t, %1; cvt.u32.u64 %0, t; }"
        : "=r"(a) : "l"(p));
    return a;
}
__device__ __forceinline__ void cp_async16(uint32_t saddr, const void* gaddr) {
    asm volatile("cp.async.cg.shared.global [%0], [%1], 16;" :: "r"(saddr), "l"(gaddr));
}
__device__ __forceinline__ void cp_commit() {
    asm volatile("cp.async.commit_group;");
}
template <int N>
__device__ __forceinline__ void cp_wait() {
    asm volatile("cp.async.wait_group %0;" :: "n"(N));
}
__device__ __forceinline__ void ldsm_x4(uint32_t* d, uint32_t saddr) {
    asm volatile("ldmatrix.sync.aligned.m8n8.x4.shared.b16 {%0,%1,%2,%3}, [%4];"
        : "=r"(d[0]), "=r"(d[1]), "=r"(d[2]), "=r"(d[3]) : "r"(saddr));
}
__device__ __forceinline__ void mma_bf16(float* c, const uint32_t* a, const uint32_t* b) {
    asm volatile(
        "mma.sync.aligned.m16n8k16.row.col.f32.bf16.bf16.f32 "
        "{%0,%1,%2,%3}, {%4,%5,%6,%7}, {%8,%9}, {%0,%1,%2,%3};"
        : "+f"(c[0]), "+f"(c[1]), "+f"(c[2]), "+f"(c[3])
        : "r"(a[0]), "r"(a[1]), "r"(a[2]), "r"(a[3]), "r"(b[0]), "r"(b[1]));
}
__device__ __forceinline__ void split_pack(float x0, float x1, uint32_t& h, uint32_t& l) {
    __nv_bfloat16 h0 = __float2bfloat16_rn(x0), h1 = __float2bfloat16_rn(x1);
    float r0 = x0 - __bfloat162float(h0), r1 = x1 - __bfloat162float(h1);
    __nv_bfloat16 l0 = __float2bfloat16_rn(r0), l1 = __float2bfloat16_rn(r1);
    h = (uint32_t)__bfloat16_as_ushort(h0) | ((uint32_t)__bfloat16_as_ushort(h1) << 16);
    l = (uint32_t)__bfloat16_as_ushort(l0) | ((uint32_t)__bfloat16_as_ushort(l1) << 16);
}

// ============== bf16 split conversions ==============
__global__ void split_bf16s(const float4* __restrict__ x,
                            __nv_bfloat162* __restrict__ hi,
                            __nv_bfloat162* __restrict__ lo, int n4, float scale)
{
    int i = blockIdx.x * blockDim.x + threadIdx.x;
    if (i >= n4) return;
    float4 v = x[i];
    v.x *= scale; v.y *= scale; v.z *= scale; v.w *= scale;
    __nv_bfloat16 h0 = __float2bfloat16_rn(v.x);
    __nv_bfloat16 h1 = __float2bfloat16_rn(v.y);
    __nv_bfloat16 h2 = __float2bfloat16_rn(v.z);
    __nv_bfloat16 h3 = __float2bfloat16_rn(v.w);
    __nv_bfloat16 l0 = __float2bfloat16_rn(v.x - __bfloat162float(h0));
    __nv_bfloat16 l1 = __float2bfloat16_rn(v.y - __bfloat162float(h1));
    __nv_bfloat16 l2 = __float2bfloat16_rn(v.z - __bfloat162float(h2));
    __nv_bfloat16 l3 = __float2bfloat16_rn(v.w - __bfloat162float(h3));
    hi[2 * i + 0] = __nv_bfloat162(h0, h1);
    hi[2 * i + 1] = __nv_bfloat162(h2, h3);
    lo[2 * i + 0] = __nv_bfloat162(l0, l1);
    lo[2 * i + 1] = __nv_bfloat162(l2, l3);
}

// W[K][N] fp32 -> hi/lo[N][K] bf16 (transpose + split)
__global__ void splitT_bf16(const float* __restrict__ W,
                            __nv_bfloat16* __restrict__ hi,
                            __nv_bfloat16* __restrict__ lo)
{
    __shared__ float t[32][33];
    int n0 = blockIdx.x * 32, k0 = blockIdx.y * 32;
    int tx = threadIdx.x, ty = threadIdx.y;  // (32, 8)
#pragma unroll
    for (int r = 0; r < 4; r++)
        t[ty + 8 * r][tx] = W[(size_t)(k0 + ty + 8 * r) * D_MODEL + n0 + tx];
    __syncthreads();
#pragma unroll
    for (int r = 0; r < 4; r++) {
        float v = t[tx][ty + 8 * r];
        __nv_bfloat16 h = __float2bfloat16_rn(v);
        __nv_bfloat16 l = __float2bfloat16_rn(v - __bfloat162float(h));
        size_t o = (size_t)(n0 + ty + 8 * r) * D_MODEL + k0 + tx;
        hi[o] = h;
        lo[o] = l;
    }
}

// V[b,s,h*64+d] fp32 -> Vt[b,h,d,s] bf16 hi/lo (transpose + split)
__global__ void splitT_v(const float* __restrict__ V,
                         __nv_bfloat16* __restrict__ hi,
                         __nv_bfloat16* __restrict__ lo)
{
    __shared__ float t[32][33];
    int c0 = blockIdx.x * 32;   // column (h*64+d) base
    int r0 = blockIdx.y * 32;   // row (b*SEQ+s) base
    int tx = threadIdx.x, ty = threadIdx.y;  // (32, 8)
#pragma unroll
    for (int r = 0; r < 4; r++)
        t[ty + 8 * r][tx] = V[(size_t)(r0 + ty + 8 * r) * D_MODEL + c0 + tx];
    __syncthreads();
    int bb = r0 >> 11;          // batch
    int sb = r0 & (SEQ - 1);    // s base
#pragma unroll
    for (int r = 0; r < 4; r++) {
        int col = c0 + ty + 8 * r;
        float v = t[tx][ty + 8 * r];   // = V[r0+tx][col]
        __nv_bfloat16 h = __float2bfloat16_rn(v);
        __nv_bfloat16 l = __float2bfloat16_rn(v - __bfloat162float(h));
        size_t o = ((size_t)(bb * 1024 + col)) * SEQ + sb + tx;
        hi[o] = h;
        lo[o] = l;
    }
}

// ============== mma.sync bf16-split GEMM: C[M,N] = A @ Bt^T + bias ============
#define TBM 128
#define TBN 128
#define TBK 32
#define LDE   40
#define ROWB  (LDE * 2)           // 80 bytes
#define TILE_B  (TBM * ROWB)      // 10240 B per tile
#define STAGE_B (4 * TILE_B)      // 40960 B per stage
#define GEMM_SMEM (2 * STAGE_B)   // 81920 B
#define KCH (D_MODEL / TBK)       // 32 chunks

__global__ __launch_bounds__(256) void gemm_bf16split(
    const __nv_bfloat16* __restrict__ Ah, const __nv_bfloat16* __restrict__ Al,
    const __nv_bfloat16* __restrict__ Bh, const __nv_bfloat16* __restrict__ Bl,
    const float* __restrict__ bias, float* __restrict__ C)
{
    extern __shared__ char smem[];
    const uint32_t sbase = smem_u32(smem);
    const int tid  = threadIdx.x;
    const int wid  = tid >> 5;
    const int lane = tid & 31;
    const int row0 = blockIdx.y * TBM;
    const int col0 = blockIdx.x * TBN;
    const int K = D_MODEL, N = D_MODEL;

    const int wr = (wid >> 1) * 32;
    const int wc = (wid & 1) * 64;

    const int r_ld  = tid >> 2;
    const int c_ld  = (tid & 3) * 16;
    const int c_el  = (tid & 3) * 8;

    float acc[2][8][4];
#pragma unroll
    for (int mi = 0; mi < 2; mi++)
#pragma unroll
        for (int ni = 0; ni < 8; ni++)
#pragma unroll
            for (int q = 0; q < 4; q++) acc[mi][ni][q] = 0.f;

    auto load_chunk = [&](int kc, int s) {
        uint32_t st = sbase + s * STAGE_B;
#pragma unroll
        for (int t = 0; t < 2; t++) {
            int r = r_ld + t * 64;
            uint32_t so = r * ROWB + c_ld;
            size_t ga = (size_t)(row0 + r) * K + kc + c_el;
            size_t gb = (size_t)(col0 + r) * K + kc + c_el;
            cp_async16(st + 0 * TILE_B + so, Ah + ga);
            cp_async16(st + 1 * TILE_B + so, Al + ga);
            cp_async16(st + 2 * TILE_B + so, Bh + gb);
            cp_async16(st + 3 * TILE_B + so, Bl + gb);
        }
        cp_commit();
    };

    load_chunk(0, 0);

    for (int i = 0; i < KCH; i++) {
        if (i + 1 < KCH) {
            load_chunk((i + 1) * TBK, (i + 1) & 1);
            cp_wait<1>();
        } else {
            cp_wait<0>();
        }
        __syncthreads();

        const uint32_t st = sbase + (i & 1) * STAGE_B;

#pragma unroll
        for (int k16 = 0; k16 < 2; k16++) {
            const int ko = k16 * 16;
            uint32_t ah[2][4], al[2][4];
#pragma unroll
            for (int mi = 0; mi < 2; mi++) {
                uint32_t ao = (uint32_t)(wr + mi * 16 + (lane & 15)) * ROWB
                            + (uint32_t)(ko + ((lane >> 4) << 3)) * 2;
                ldsm_x4(ah[mi], st + 0 * TILE_B + ao);
                ldsm_x4(al[mi], st + 1 * TILE_B + ao);
            }
#pragma unroll
            for (int np = 0; np < 4; np++) {
                uint32_t bo = (uint32_t)(wc + np * 16 + ((lane >> 4) << 3) + (lane & 7)) * ROWB
                            + (uint32_t)(ko + (((lane >> 3) & 1) << 3)) * 2;
                uint32_t bh[4], bl[4];
                ldsm_x4(bh, st + 2 * TILE_B + bo);
                ldsm_x4(bl, st + 3 * TILE_B + bo);
#pragma unroll
                for (int mi = 0; mi < 2; mi++) {
                    mma_bf16(acc[mi][2 * np + 0], ah[mi], bh + 0);
                    mma_bf16(acc[mi][2 * np + 1], ah[mi], bh + 2);
                    mma_bf16(acc[mi][2 * np + 0], ah[mi], bl + 0);
                    mma_bf16(acc[mi][2 * np + 1], ah[mi], bl + 2);
                    mma_bf16(acc[mi][2 * np + 0], al[mi], bh + 0);
                    mma_bf16(acc[mi][2 * np + 1], al[mi], bh + 2);
                }
            }
        }
        __syncthreads();
    }

    const int r_in = lane >> 2;
    const int c_in = (lane & 3) * 2;
#pragma unroll
    for (int mi = 0; mi < 2; mi++) {
#pragma unroll
        for (int ni = 0; ni < 8; ni++) {
            int col = col0 + wc + ni * 8 + c_in;
            float b0 = bias[col], b1 = bias[col + 1];
            int row = row0 + wr + mi * 16 + r_in;
            float2 o0 = make_float2(acc[mi][ni][0] + b0, acc[mi][ni][1] + b1);
            float2 o1 = make_float2(acc[mi][ni][2] + b0, acc[mi][ni][3] + b1);
            *(float2*)&C[(size_t)row * N + col] = o0;
            *(float2*)&C[(size_t)(row + 8) * N + col] = o1;
        }
    }
}

// ---------------- RoPE table + apply ------------------------------------------
__global__ void rope_table_kernel()
{
    int idx = blockIdx.x * blockDim.x + threadIdx.x;
    if (idx >= SEQ * 32) return;
    int j = idx & 31;
    int t = idx >> 5;
    double e = exp(-(double)j * (9.210340371976184 / 32.0));
    float ang = (float)t * (float)e;
    g_cos[idx] = cosf(ang);
    g_sin[idx] = sinf(ang);
}

__global__ void rope_kernel(float* __restrict__ Q, float* __restrict__ K)
{
    int idx = blockIdx.x * blockDim.x + threadIdx.x;
    if (idx >= M_TOT * NUM_HEADS * (HEAD_DIM / 2)) return;
    int j   = idx & 31;
    int h   = (idx >> 5) & (NUM_HEADS - 1);
    int row = idx >> 9;
    int t   = row & (SEQ - 1);

    float c = g_cos[t * 32 + j];
    float s = g_sin[t * 32 + j];

    size_t base = (size_t)row * D_MODEL + h * HEAD_DIM + j;
    float q1 = Q[base], q2 = Q[base + 32];
    Q[base]      = q1 * c - q2 * s;
    Q[base + 32] = q2 * c + q1 * s;
    float k1 = K[base], k2 = K[base + 32];
    K[base]      = k1 * c - k2 * s;
    K[base + 32] = k2 * c + k1 * s;
}

// ---------------- Flash attention on HMMA, bf16 3-term split -------------------
// Br=128 (8 warps x m16), Bc=64, head dim 64.
#define FROWB  144                         // 64 bf16 (128B) + 16B pad
#define FQ_BYTES (128 * FROWB)             // 18432
#define FK_BYTES (64 * FROWB)              // 9216
#define FSTG_B   (4 * FK_BYTES)            // 36864 (Kh,Kl,Vh,Vl)
#define FLASH_SMEM (2 * FQ_BYTES + 2 * FSTG_B)  // 110592
#define NKV (SEQ / 64)                     // 32

__global__ __launch_bounds__(256) void flash_hmma(
    const __nv_bfloat16* __restrict__ Qh, const __nv_bfloat16* __restrict__ Ql,
    const __nv_bfloat16* __restrict__ Kh, const __nv_bfloat16* __restrict__ Kl,
    const __nv_bfloat16* __restrict__ Vh, const __nv_bfloat16* __restrict__ Vl,
    float* __restrict__ Cp)
{
    extern __shared__ char smem[];
    const uint32_t sbase = smem_u32(smem);
    const int tid  = threadIdx.x;
    const int wid  = tid >> 5;
    const int lane = tid & 31;
    const int g    = lane >> 2;
    const int tg   = lane & 3;
    const int q0   = blockIdx.x * 128;
    const int h    = blockIdx.y;
    const int b    = blockIdx.z;

    // ---- Q tile load (hi/lo): 128 rows x 128B = 1024 cp16 per tile ----
#pragma unroll
    for (int t = 0; t < 4; t++) {
        int idx = tid + t * 256;           // 0..1023
        int r = idx >> 3, seg = idx & 7;
        uint32_t so = r * FROWB + seg * 16;
        size_t gq = (size_t)(b * SEQ + q0 + r) * D_MODEL + h * 64 + seg * 8;
        cp_async16(sbase + 0 * FQ_BYTES + so, Qh + gq);
        cp_async16(sbase + 1 * FQ_BYTES + so, Ql + gq);
    }
    cp_commit();

    auto load_kv = [&](int s0, int stg) {
        uint32_t st = sbase + 2 * FQ_BYTES + stg * FSTG_B;
#pragma unroll
        for (int t = 0; t < 2; t++) {
            int idx = tid + t * 256;       // 0..511
            int r = idx >> 3, seg = idx & 7;   // r: s-row for K, d-row for V
            uint32_t so = r * FROWB + seg * 16;
            size_t gk = (size_t)(b * SEQ + s0 + r) * D_MODEL + h * 64 + seg * 8;
            size_t gv = ((size_t)(b * 1024 + h * 64 + r)) * SEQ + s0 + seg * 8;
            cp_async16(st + 0 * FK_BYTES + so, Kh + gk);
            cp_async16(st + 1 * FK_BYTES + so, Kl + gk);
            cp_async16(st + 2 * FK_BYTES + so, Vh + gv);
            cp_async16(st + 3 * FK_BYTES + so, Vl + gv);
        }
        cp_commit();
    };

    load_kv(0, 0);

    // wait for Q (allow stage0 pending), then pull Q fragments to registers
    cp_wait<1>();
    __syncthreads();
    uint32_t qh[4][4], ql[4][4];
#pragma unroll
    for (int k16 = 0; k16 < 4; k16++) {
        uint32_t ao = (uint32_t)(wid * 16 + (lane & 15)) * FROWB
                    + (uint32_t)(k16 * 16 + ((lane >> 4) << 3)) * 2;
        ldsm_x4(qh[k16], sbase + 0 * FQ_BYTES + ao);
        ldsm_x4(ql[k16], sbase + 1 * FQ_BYTES + ao);
    }

    float m[2] = {-1e30f, -1e30f};
    float l[2] = {0.f, 0.f};
    float oacc[8][4];
#pragma unroll
    for (int nt = 0; nt < 8; nt++)
#pragma unroll
        for (int q = 0; q < 4; q++) oacc[nt][q] = 0.f;

    for (int it = 0; it < NKV; it++) {
        if (it + 1 < NKV) {
            load_kv((it + 1) * 64, (it + 1) & 1);
            cp_wait<1>();
        } else {
            cp_wait<0>();
        }
        __syncthreads();   // stage `it` data visible to all

        const uint32_t st = sbase + 2 * FQ_BYTES + (it & 1) * FSTG_B;

        // ---- S = Q K^T (3-term split) ----
        float sacc[8][4];
#pragma unroll
        for (int nt = 0; nt < 8; nt++)
#pragma unroll
            for (int q = 0; q < 4; q++) sacc[nt][q] = 0.f;

#pragma unroll
        for (int k16 = 0; k16 < 4; k16++) {
            uint32_t bh[4][4], bl[4][4];
#pragma unroll
            for (int np = 0; np < 4; np++) {
                uint32_t bo = (uint32_t)(np * 16 + ((lane >> 4) << 3) + (lane & 7)) * FROWB
                            + (uint32_t)(k16 * 16 + (((lane >> 3) & 1) << 3)) * 2;
                ldsm_x4(bh[np], st + 0 * FK_BYTES + bo);
                ldsm_x4(bl[np], st + 1 * FK_BYTES + bo);
            }
#pragma unroll
            for (int np = 0; np < 4; np++) {
                mma_bf16(sacc[2 * np + 0], qh[k16], bh[np] + 0);
                mma_bf16(sacc[2 * np + 1], qh[k16], bh[np] + 2);
            }
#pragma unroll
            for (int np = 0; np < 4; np++) {
                mma_bf16(sacc[2 * np + 0], qh[k16], bl[np] + 0);
                mma_bf16(sacc[2 * np + 1], qh[k16], bl[np] + 2);
            }
#pragma unroll
            for (int np = 0; np < 4; np++) {
                mma_bf16(sacc[2 * np + 0], ql[k16], bh[np] + 0);
                mma_bf16(sacc[2 * np + 1], ql[k16], bh[np] + 2);
            }
        }

        // ---- online softmax (rows g, g+8; lanes sharing g: xor 1,2) ----
#pragma unroll
        for (int rr = 0; rr < 2; rr++) {
            float mx = -1e30f;
#pragma unroll
            for (int nt = 0; nt < 8; nt++)
                mx = fmaxf(mx, fmaxf(sacc[nt][2 * rr], sacc[nt][2 * rr + 1]));
            mx = fmaxf(mx, __shfl_xor_sync(0xffffffffu, mx, 1));
            mx = fmaxf(mx, __shfl_xor_sync(0xffffffffu, mx, 2));
            float mn = fmaxf(m[rr], mx);
            float alpha = __expf(m[rr] - mn);
            m[rr] = mn;
            float su = 0.f;
#pragma unroll
            for (int nt = 0; nt < 8; nt++) {
                float p0 = __expf(sacc[nt][2 * rr] - mn);
                float p1 = __expf(sacc[nt][2 * rr + 1] - mn);
                sacc[nt][2 * rr] = p0;
                sacc[nt][2 * rr + 1] = p1;
                su += p0 + p1;
            }
            su += __shfl_xor_sync(0xffffffffu, su, 1);
            su += __shfl_xor_sync(0xffffffffu, su, 2);
            l[rr] = l[rr] * alpha + su;
#pragma unroll
            for (int nt = 0; nt < 8; nt++) {
                oacc[nt][2 * rr]     *= alpha;
                oacc[nt][2 * rr + 1] *= alpha;
            }
        }

        // ---- P -> A fragments (hi/lo), register-local ----
        uint32_t ph[4][4], pl[4][4];
#pragma unroll
        for (int j = 0; j < 4; j++) {
            split_pack(sacc[2 * j][0],     sacc[2 * j][1],     ph[j][0], pl[j][0]);
            split_pack(sacc[2 * j][2],     sacc[2 * j][3],     ph[j][1], pl[j][1]);
            split_pack(sacc[2 * j + 1][0], sacc[2 * j + 1][1], ph[j][2], pl[j][2]);
            split_pack(sacc[2 * j + 1][2], sacc[2 * j + 1][3], ph[j][3], pl[j][3]);
        }

        // ---- O += P V (3-term split); V tile is [d][s] so B-frags like GEMM ----
#pragma unroll
        for (int j = 0; j < 4; j++) {
            uint32_t vh[4][4], vl[4][4];
#pragma unroll
            for (int np = 0; np < 4; np++) {
                uint32_t bo = (uint32_t)(np * 16 + ((lane >> 4) << 3) + (lane & 7)) * FROWB
                            + (uint32_t)(j * 16 + (((lane >> 3) & 1) << 3)) * 2;
                ldsm_x4(vh[np], st + 2 * FK_BYTES + bo);
                ldsm_x4(vl[np], st + 3 * FK_BYTES + bo);
            }
#pragma unroll
            for (int np = 0; np < 4; np++) {
                mma_bf16(oacc[2 * np + 0], ph[j], vh[np] + 0);
                mma_bf16(oacc[2 * np + 1], ph[j], vh[np] + 2);
            }
#pragma unroll
            for (int np = 0; np < 4; np++) {
                mma_bf16(oacc[2 * np + 0], ph[j], vl[np] + 0);
                mma_bf16(oacc[2 * np + 1], ph[j], vl[np] + 2);
            }
#pragma unroll
            for (int np = 0; np < 4; np++) {
                mma_bf16(oacc[2 * np + 0], pl[j], vh[np] + 0);
                mma_bf16(oacc[2 * np + 1], pl[j], vh[np] + 2);
            }
        }
        __syncthreads();   // everyone done reading stage `it`
    }

    // ---- normalize + write ----
    float inv0 = 1.f / l[0], inv1 = 1.f / l[1];
    int rowg = b * SEQ + q0 + wid * 16 + g;
#pragma unroll
    for (int nt = 0; nt < 8; nt++) {
        int col = h * 64 + nt * 8 + 2 * tg;
        *(float2*)&Cp[(size_t)rowg * D_MODEL + col] =
            make_float2(oacc[nt][0] * inv0, oacc[nt][1] * inv0);
        *(float2*)&Cp[(size_t)(rowg + 8) * D_MODEL + col] =
            make_float2(oacc[nt][2] * inv1, oacc[nt][3] * inv1);
    }
}

// ---------------- launch --------------------------------------------------------
extern "C" void kernel_launch(void* const* d_in, const int* in_sizes, int n_in,
                              void* d_out, int out_size)
{
    const float* query = (const float*)d_in[0];
    const float* key   = (const float*)d_in[1];
    const float* value = (const float*)d_in[2];
    const float* Wq = (const float*)d_in[3];
    const float* bq = (const float*)d_in[4];
    const float* Wk = (const float*)d_in[5];
    const float* bk = (const float*)d_in[6];
    const float* Wv = (const float*)d_in[7];
    const float* bv = (const float*)d_in[8];
    const float* Wo = (const float*)d_in[9];
    const float* bo = (const float*)d_in[10];
    float* out = (float*)d_out;
    (void)in_sizes; (void)n_in; (void)out_size;

    float *gQ, *gK, *gV, *gC;
    __nv_bfloat16 *gAh, *gAl, *gBh, *gBl;
    __nv_bfloat16 *gQh, *gQl, *gKh, *gKl, *gVth, *gVtl;
    cudaGetSymbolAddress((void**)&gQ, g_Q);
    cudaGetSymbolAddress((void**)&gK, g_K);
    cudaGetSymbolAddress((void**)&gV, g_V);
    cudaGetSymbolAddress((void**)&gC, g_C);
    cudaGetSymbolAddress((void**)&gAh, g_Ah);
    cudaGetSymbolAddress((void**)&gAl, g_Al);
    cudaGetSymbolAddress((void**)&gBh, g_Bh);
    cudaGetSymbolAddress((void**)&gBl, g_Bl);
    cudaGetSymbolAddress((void**)&gQh, g_Qh);
    cudaGetSymbolAddress((void**)&gQl, g_Ql);
    cudaGetSymbolAddress((void**)&gKh, g_Kh);
    cudaGetSymbolAddress((void**)&gKl, g_Kl);
    cudaGetSymbolAddress((void**)&gVth, g_Vth);
    cudaGetSymbolAddress((void**)&gVtl, g_Vtl);

    const int n4 = M_TOT * D_MODEL / 4;
    const dim3 tgrid(D_MODEL / 32, D_MODEL / 32);
    const dim3 tblk(32, 8);
    const dim3 ggrid(D_MODEL / TBN, M_TOT / TBM);   // (8, 64)

    cudaFuncSetAttribute(gemm_bf16split,
                         cudaFuncAttributeMaxDynamicSharedMemorySize, GEMM_SMEM);
    cudaFuncSetAttribute(flash_hmma,
                         cudaFuncAttributeMaxDynamicSharedMemorySize, FLASH_SMEM);

    rope_table_kernel<<<(SEQ * 32 + 255) / 256, 256>>>();

    // Q projection
    split_bf16s<<<(n4 + 255) / 256, 256>>>((const float4*)query,
        (__nv_bfloat162*)gAh, (__nv_bfloat162*)gAl, n4, 1.f);
    splitT_bf16<<<tgrid, tblk>>>(Wq, gBh, gBl);
    gemm_bf16split<<<ggrid, 256, GEMM_SMEM>>>(gAh, gAl, gBh, gBl, bq, gQ);
    // K projection
    split_bf16s<<<(n4 + 255) / 256, 256>>>((const float4*)key,
        (__nv_bfloat162*)gAh, (__nv_bfloat162*)gAl, n4, 1.f);
    splitT_bf16<<<tgrid, tblk>>>(Wk, gBh, gBl);
    gemm_bf16split<<<ggrid, 256, GEMM_SMEM>>>(gAh, gAl, gBh, gBl, bk, gK);
    // V projection
    split_bf16s<<<(n4 + 255) / 256, 256>>>((const float4*)value,
        (__nv_bfloat162*)gAh, (__nv_bfloat162*)gAl, n4, 1.f);
    splitT_bf16<<<tgrid, tblk>>>(Wv, gBh, gBl);
    gemm_bf16split<<<ggrid, 256, GEMM_SMEM>>>(gAh, gAl, gBh, gBl, bv, gV);

    // RoPE
    int nrope = M_TOT * NUM_HEADS * (HEAD_DIM / 2);
    rope_kernel<<<(nrope + 255) / 256, 256>>>(gQ, gK);

    // split for attention: Q (x0.125), K, V(transposed)
    split_bf16s<<<(n4 + 255) / 256, 256>>>((const float4*)gQ,
        (__nv_bfloat162*)gQh, (__nv_bfloat162*)gQl, n4, 0.125f);
    split_bf16s<<<(n4 + 255) / 256, 256>>>((const float4*)gK,
        (__nv_bfloat162*)gKh, (__nv_bfloat162*)gKl, n4, 1.f);
    splitT_v<<<dim3(D_MODEL / 32, M_TOT / 32), tblk>>>(gV, gVth, gVtl);

    // attention
    flash_hmma<<<dim3(SEQ / 128, NUM_HEADS, BATCH), 256, FLASH_SMEM>>>(
        gQh, gQl, gKh, gKl, gVth, gVtl, gC);

    // output projection
    split_bf16s<<<(n4 + 255) / 256, 256>>>((const float4*)gC,
        (__nv_bfloat162*)gAh, (__nv_bfloat162*)gAl, n4, 1.f);
    splitT_bf16<<<tgrid, tblk>>>(Wo, gBh, gBl);
    gemm_bf16split<<<ggrid, 256, GEMM_SMEM>>>(gAh, gAl, gBh, gBl, bo, out);
}

// round 6
// speedup vs baseline: 2.7349x; 1.0251x over previous
#include <cuda_runtime.h>
#include <cuda_bf16.h>
#include <math.h>
#include <stdint.h>

#define D_MODEL   1024
#define NUM_HEADS 16
#define HEAD_DIM  64
#define BATCH     4
#define SEQ       2048
#define M_TOT     (BATCH * SEQ)   // 8192

// ---------------- scratch (allocation-free rule: __device__ globals) ----------
__device__ float g_Q[(size_t)M_TOT * D_MODEL];
__device__ float g_K[(size_t)M_TOT * D_MODEL];
__device__ float g_V[(size_t)M_TOT * D_MODEL];
__device__ float g_C[(size_t)M_TOT * D_MODEL];
__device__ __nv_bfloat16 g_Ah[(size_t)M_TOT * D_MODEL];
__device__ __nv_bfloat16 g_Al[(size_t)M_TOT * D_MODEL];
__device__ __nv_bfloat16 g_Bh[(size_t)D_MODEL * D_MODEL];
__device__ __nv_bfloat16 g_Bl[(size_t)D_MODEL * D_MODEL];
__device__ __nv_bfloat16 g_Qh[(size_t)M_TOT * D_MODEL];
__device__ __nv_bfloat16 g_Ql[(size_t)M_TOT * D_MODEL];
__device__ __nv_bfloat16 g_Kh[(size_t)M_TOT * D_MODEL];
__device__ __nv_bfloat16 g_Kl[(size_t)M_TOT * D_MODEL];
__device__ __nv_bfloat16 g_Vth[(size_t)M_TOT * D_MODEL];  // [b,h,d,s]
__device__ __nv_bfloat16 g_Vtl[(size_t)M_TOT * D_MODEL];
__device__ float g_cos[SEQ * 32];
__device__ float g_sin[SEQ * 32];

// ================= helpers =================
__device__ __forceinline__ uint32_t smem_u32(const void* p) {
    uint32_t a;
    asm("{ .reg .u64 t; cvta.to.shared.u64 t, %1; cvt.u32.u64 %0, t; }"
        : "=r"(a) : "l"(p));
    return a;
}
__device__ __forceinline__ void cp_async16(uint32_t saddr, const void* gaddr) {
    asm volatile("cp.async.cg.shared.global [%0], [%1], 16;" :: "r"(saddr), "l"(gaddr));
}
__device__ __forceinline__ void cp_commit() {
    asm volatile("cp.async.commit_group;");
}
template <int N>
__device__ __forceinline__ void cp_wait() {
    asm volatile("cp.async.wait_group %0;" :: "n"(N));
}
__device__ __forceinline__ void ldsm_x4(uint32_t* d, uint32_t saddr) {
    asm volatile("ldmatrix.sync.aligned.m8n8.x4.shared.b16 {%0,%1,%2,%3}, [%4];"
        : "=r"(d[0]), "=r"(d[1]), "=r"(d[2]), "=r"(d[3]) : "r"(saddr));
}
__device__ __forceinline__ void mma_bf16(float* c, const uint32_t* a, const uint32_t* b) {
    asm volatile(
        "mma.sync.aligned.m16n8k16.row.col.f32.bf16.bf16.f32 "
        "{%0,%1,%2,%3}, {%4,%5,%6,%7}, {%8,%9}, {%0,%1,%2,%3};"
        : "+f"(c[0]), "+f"(c[1]), "+f"(c[2]), "+f"(c[3])
        : "r"(a[0]), "r"(a[1]), "r"(a[2]), "r"(a[3]), "r"(b[0]), "r"(b[1]));
}
__device__ __forceinline__ void split_pack(float x0, float x1, uint32_t& h, uint32_t& l) {
    __nv_bfloat16 h0 = __float2bfloat16_rn(x0), h1 = __float2bfloat16_rn(x1);
    float r0 = x0 - __bfloat162float(h0), r1 = x1 - __bfloat162float(h1);
    __nv_bfloat16 l0 = __float2bfloat16_rn(r0), l1 = __float2bfloat16_rn(r1);
    h = (uint32_t)__bfloat16_as_ushort(h0) | ((uint32_t)__bfloat16_as_ushort(h1) << 16);
    l = (uint32_t)__bfloat16_as_ushort(l0) | ((uint32_t)__bfloat16_as_ushort(l1) << 16);
}
__device__ __forceinline__ void split1(float x, __nv_bfloat16& h, __nv_bfloat16& l) {
    h = __float2bfloat16_rn(x);
    l = __float2bfloat16_rn(x - __bfloat162float(h));
}

// ============== bf16 split conversions ==============
__global__ void split_bf16s(const float4* __restrict__ x,
                            __nv_bfloat162* __restrict__ hi,
                            __nv_bfloat162* __restrict__ lo, int n4, float scale)
{
    int i = blockIdx.x * blockDim.x + threadIdx.x;
    if (i >= n4) return;
    float4 v = x[i];
    v.x *= scale; v.y *= scale; v.z *= scale; v.w *= scale;
    __nv_bfloat16 h0, h1, h2, h3, l0, l1, l2, l3;
    split1(v.x, h0, l0); split1(v.y, h1, l1);
    split1(v.z, h2, l2); split1(v.w, h3, l3);
    hi[2 * i + 0] = __nv_bfloat162(h0, h1);
    hi[2 * i + 1] = __nv_bfloat162(h2, h3);
    lo[2 * i + 0] = __nv_bfloat162(l0, l1);
    lo[2 * i + 1] = __nv_bfloat162(l2, l3);
}

// W[K][N] fp32 -> hi/lo[N][K] bf16 (transpose + split)
__global__ void splitT_bf16(const float* __restrict__ W,
                            __nv_bfloat16* __restrict__ hi,
                            __nv_bfloat16* __restrict__ lo)
{
    __shared__ float t[32][33];
    int n0 = blockIdx.x * 32, k0 = blockIdx.y * 32;
    int tx = threadIdx.x, ty = threadIdx.y;  // (32, 8)
#pragma unroll
    for (int r = 0; r < 4; r++)
        t[ty + 8 * r][tx] = W[(size_t)(k0 + ty + 8 * r) * D_MODEL + n0 + tx];
    __syncthreads();
#pragma unroll
    for (int r = 0; r < 4; r++) {
        float v = t[tx][ty + 8 * r];
        __nv_bfloat16 h, l;
        split1(v, h, l);
        size_t o = (size_t)(n0 + ty + 8 * r) * D_MODEL + k0 + tx;
        hi[o] = h;
        lo[o] = l;
    }
}

// V[b,s,h*64+d] fp32 -> Vt[b,h,d,s] bf16 hi/lo (transpose + split)
__global__ void splitT_v(const float* __restrict__ V,
                         __nv_bfloat16* __restrict__ hi,
                         __nv_bfloat16* __restrict__ lo)
{
    __shared__ float t[32][33];
    int c0 = blockIdx.x * 32;
    int r0 = blockIdx.y * 32;
    int tx = threadIdx.x, ty = threadIdx.y;  // (32, 8)
#pragma unroll
    for (int r = 0; r < 4; r++)
        t[ty + 8 * r][tx] = V[(size_t)(r0 + ty + 8 * r) * D_MODEL + c0 + tx];
    __syncthreads();
    int bb = r0 >> 11;
    int sb = r0 & (SEQ - 1);
#pragma unroll
    for (int r = 0; r < 4; r++) {
        int col = c0 + ty + 8 * r;
        float v = t[tx][ty + 8 * r];
        __nv_bfloat16 h, l;
        split1(v, h, l);
        size_t o = ((size_t)(bb * 1024 + col)) * SEQ + sb + tx;
        hi[o] = h;
        lo[o] = l;
    }
}

// ============== mma.sync bf16-split GEMM: C[M,N] = A @ Bt^T + bias ============
#define TBM 128
#define TBN 128
#define TBK 64
#define ROWB  144                 // 64 bf16 (128B) + 16B pad
#define TILE_B  (TBM * ROWB)      // 18432 B per tile
#define STAGE_B (4 * TILE_B)      // 73728 B per stage
#define GEMM_SMEM (2 * STAGE_B)   // 147456 B
#define KCH (D_MODEL / TBK)       // 16 chunks

__global__ __launch_bounds__(256) void gemm_bf16split(
    const __nv_bfloat16* __restrict__ Ah, const __nv_bfloat16* __restrict__ Al,
    const __nv_bfloat16* __restrict__ Bh, const __nv_bfloat16* __restrict__ Bl,
    const float* __restrict__ bias, float* __restrict__ C)
{
    extern __shared__ char smem[];
    const uint32_t sbase = smem_u32(smem);
    const int tid  = threadIdx.x;
    const int wid  = tid >> 5;
    const int lane = tid & 31;
    const int row0 = blockIdx.y * TBM;
    const int col0 = blockIdx.x * TBN;
    const int K = D_MODEL, N = D_MODEL;

    const int wr = (wid >> 1) * 32;
    const int wc = (wid & 1) * 64;

    float acc[2][8][4];
#pragma unroll
    for (int mi = 0; mi < 2; mi++)
#pragma unroll
        for (int ni = 0; ni < 8; ni++)
#pragma unroll
            for (int q = 0; q < 4; q++) acc[mi][ni][q] = 0.f;

    // loads: 128 rows x 8 segs = 1024 cp16 per tile => 4 rounds x 256 threads
    auto load_chunk = [&](int kc, int s) {
        uint32_t st = sbase + s * STAGE_B;
#pragma unroll
        for (int t = 0; t < 4; t++) {
            int idx = tid + t * 256;
            int r = idx >> 3, seg = idx & 7;
            uint32_t so = r * ROWB + seg * 16;
            size_t ga = (size_t)(row0 + r) * K + kc + seg * 8;
            size_t gb = (size_t)(col0 + r) * K + kc + seg * 8;
            cp_async16(st + 0 * TILE_B + so, Ah + ga);
            cp_async16(st + 1 * TILE_B + so, Al + ga);
            cp_async16(st + 2 * TILE_B + so, Bh + gb);
            cp_async16(st + 3 * TILE_B + so, Bl + gb);
        }
        cp_commit();
    };

    load_chunk(0, 0);

    for (int i = 0; i < KCH; i++) {
        if (i + 1 < KCH) {
            load_chunk((i + 1) * TBK, (i + 1) & 1);
            cp_wait<1>();
        } else {
            cp_wait<0>();
        }
        __syncthreads();

        const uint32_t st = sbase + (i & 1) * STAGE_B;

#pragma unroll
        for (int k16 = 0; k16 < 4; k16++) {
            const int ko = k16 * 16;
            // preload ALL fragments for this k16
            uint32_t ah[2][4], al[2][4], bh[4][4], bl[4][4];
#pragma unroll
            for (int mi = 0; mi < 2; mi++) {
                uint32_t ao = (uint32_t)(wr + mi * 16 + (lane & 15)) * ROWB
                            + (uint32_t)(ko + ((lane >> 4) << 3)) * 2;
                ldsm_x4(ah[mi], st + 0 * TILE_B + ao);
                ldsm_x4(al[mi], st + 1 * TILE_B + ao);
            }
#pragma unroll
            for (int np = 0; np < 4; np++) {
                uint32_t bo = (uint32_t)(wc + np * 16 + ((lane >> 4) << 3) + (lane & 7)) * ROWB
                            + (uint32_t)(ko + (((lane >> 3) & 1) << 3)) * 2;
                ldsm_x4(bh[np], st + 2 * TILE_B + bo);
                ldsm_x4(bl[np], st + 3 * TILE_B + bo);
            }
            // term-major: same-accumulator reuse distance = 16 MMAs
#pragma unroll
            for (int np = 0; np < 4; np++)
#pragma unroll
                for (int mi = 0; mi < 2; mi++) {
                    mma_bf16(acc[mi][2 * np + 0], ah[mi], bh[np] + 0);
                    mma_bf16(acc[mi][2 * np + 1], ah[mi], bh[np] + 2);
                }
#pragma unroll
            for (int np = 0; np < 4; np++)
#pragma unroll
                for (int mi = 0; mi < 2; mi++) {
                    mma_bf16(acc[mi][2 * np + 0], ah[mi], bl[np] + 0);
                    mma_bf16(acc[mi][2 * np + 1], ah[mi], bl[np] + 2);
                }
#pragma unroll
            for (int np = 0; np < 4; np++)
#pragma unroll
                for (int mi = 0; mi < 2; mi++) {
                    mma_bf16(acc[mi][2 * np + 0], al[mi], bh[np] + 0);
                    mma_bf16(acc[mi][2 * np + 1], al[mi], bh[np] + 2);
                }
        }
        __syncthreads();
    }

    const int r_in = lane >> 2;
    const int c_in = (lane & 3) * 2;
#pragma unroll
    for (int mi = 0; mi < 2; mi++) {
#pragma unroll
        for (int ni = 0; ni < 8; ni++) {
            int col = col0 + wc + ni * 8 + c_in;
            float b0 = bias[col], b1 = bias[col + 1];
            int row = row0 + wr + mi * 16 + r_in;
            float2 o0 = make_float2(acc[mi][ni][0] + b0, acc[mi][ni][1] + b1);
            float2 o1 = make_float2(acc[mi][ni][2] + b0, acc[mi][ni][3] + b1);
            *(float2*)&C[(size_t)row * N + col] = o0;
            *(float2*)&C[(size_t)(row + 8) * N + col] = o1;
        }
    }
}

// ---------------- RoPE table ---------------------------------------------------
__global__ void rope_table_kernel()
{
    int idx = blockIdx.x * blockDim.x + threadIdx.x;
    if (idx >= SEQ * 32) return;
    int j = idx & 31;
    int t = idx >> 5;
    double e = exp(-(double)j * (9.210340371976184 / 32.0));
    float ang = (float)t * (float)e;
    g_cos[idx] = cosf(ang);
    g_sin[idx] = sinf(ang);
}

// ---------------- fused RoPE + bf16 split for Q (x0.125) and K ------------------
__global__ void rope_split(const float* __restrict__ Q, const float* __restrict__ K,
                           __nv_bfloat16* __restrict__ Qh, __nv_bfloat16* __restrict__ Ql,
                           __nv_bfloat16* __restrict__ Kh, __nv_bfloat16* __restrict__ Kl)
{
    int idx = blockIdx.x * blockDim.x + threadIdx.x;
    if (idx >= M_TOT * NUM_HEADS * (HEAD_DIM / 2)) return;
    int j   = idx & 31;
    int h   = (idx >> 5) & (NUM_HEADS - 1);
    int row = idx >> 9;
    int t   = row & (SEQ - 1);

    float c = g_cos[t * 32 + j];
    float s = g_sin[t * 32 + j];

    size_t base = (size_t)row * D_MODEL + h * HEAD_DIM + j;
    float q1 = Q[base], q2 = Q[base + 32];
    float qa = (q1 * c - q2 * s) * 0.125f;
    float qb = (q2 * c + q1 * s) * 0.125f;
    __nv_bfloat16 hh, ll;
    split1(qa, hh, ll); Qh[base] = hh;      Ql[base] = ll;
    split1(qb, hh, ll); Qh[base + 32] = hh; Ql[base + 32] = ll;

    float k1 = K[base], k2 = K[base + 32];
    float ka = k1 * c - k2 * s;
    float kb = k2 * c + k1 * s;
    split1(ka, hh, ll); Kh[base] = hh;      Kl[base] = ll;
    split1(kb, hh, ll); Kh[base + 32] = hh; Kl[base + 32] = ll;
}

// ---------------- Flash attention on HMMA, bf16 3-term split -------------------
// Br=128 (8 warps x m16), Bc=64, head dim 64.
#define FROWB  144                         // 64 bf16 (128B) + 16B pad
#define FQ_BYTES (128 * FROWB)             // 18432
#define FK_BYTES (64 * FROWB)              // 9216
#define FSTG_B   (4 * FK_BYTES)            // 36864 (Kh,Kl,Vh,Vl)
#define FLASH_SMEM (2 * FQ_BYTES + 2 * FSTG_B)  // 110592
#define NKV (SEQ / 64)                     // 32

__global__ __launch_bounds__(256) void flash_hmma(
    const __nv_bfloat16* __restrict__ Qh, const __nv_bfloat16* __restrict__ Ql,
    const __nv_bfloat16* __restrict__ Kh, const __nv_bfloat16* __restrict__ Kl,
    const __nv_bfloat16* __restrict__ Vh, const __nv_bfloat16* __restrict__ Vl,
    float* __restrict__ Cp)
{
    extern __shared__ char smem[];
    const uint32_t sbase = smem_u32(smem);
    const int tid  = threadIdx.x;
    const int wid  = tid >> 5;
    const int lane = tid & 31;
    const int g    = lane >> 2;
    const int tg   = lane & 3;
    const int q0   = blockIdx.x * 128;
    const int h    = blockIdx.y;
    const int b    = blockIdx.z;

    // ---- Q tile load (hi/lo): 128 rows x 128B = 1024 cp16 per tile ----
#pragma unroll
    for (int t = 0; t < 4; t++) {
        int idx = tid + t * 256;
        int r = idx >> 3, seg = idx & 7;
        uint32_t so = r * FROWB + seg * 16;
        size_t gq = (size_t)(b * SEQ + q0 + r) * D_MODEL + h * 64 + seg * 8;
        cp_async16(sbase + 0 * FQ_BYTES + so, Qh + gq);
        cp_async16(sbase + 1 * FQ_BYTES + so, Ql + gq);
    }
    cp_commit();

    auto load_kv = [&](int s0, int stg) {
        uint32_t st = sbase + 2 * FQ_BYTES + stg * FSTG_B;
#pragma unroll
        for (int t = 0; t < 2; t++) {
            int idx = tid + t * 256;
            int r = idx >> 3, seg = idx & 7;
            uint32_t so = r * FROWB + seg * 16;
            size_t gk = (size_t)(b * SEQ + s0 + r) * D_MODEL + h * 64 + seg * 8;
            size_t gv = ((size_t)(b * 1024 + h * 64 + r)) * SEQ + s0 + seg * 8;
            cp_async16(st + 0 * FK_BYTES + so, Kh + gk);
            cp_async16(st + 1 * FK_BYTES + so, Kl + gk);
            cp_async16(st + 2 * FK_BYTES + so, Vh + gv);
            cp_async16(st + 3 * FK_BYTES + so, Vl + gv);
        }
        cp_commit();
    };

    load_kv(0, 0);

    cp_wait<1>();
    __syncthreads();
    uint32_t qh[4][4], ql[4][4];
#pragma unroll
    for (int k16 = 0; k16 < 4; k16++) {
        uint32_t ao = (uint32_t)(wid * 16 + (lane & 15)) * FROWB
                    + (uint32_t)(k16 * 16 + ((lane >> 4) << 3)) * 2;
        ldsm_x4(qh[k16], sbase + 0 * FQ_BYTES + ao);
        ldsm_x4(ql[k16], sbase + 1 * FQ_BYTES + ao);
    }

    float m[2] = {-1e30f, -1e30f};
    float l[2] = {0.f, 0.f};
    float oacc[8][4];
#pragma unroll
    for (int nt = 0; nt < 8; nt++)
#pragma unroll
        for (int q = 0; q < 4; q++) oacc[nt][q] = 0.f;

    for (int it = 0; it < NKV; it++) {
        if (it + 1 < NKV) {
            load_kv((it + 1) * 64, (it + 1) & 1);
            cp_wait<1>();
        } else {
            cp_wait<0>();
        }
        __syncthreads();

        const uint32_t st = sbase + 2 * FQ_BYTES + (it & 1) * FSTG_B;

        // ---- S = Q K^T (3-term split) ----
        float sacc[8][4];
#pragma unroll
        for (int nt = 0; nt < 8; nt++)
#pragma unroll
            for (int q = 0; q < 4; q++) sacc[nt][q] = 0.f;

#pragma unroll
        for (int k16 = 0; k16 < 4; k16++) {
            uint32_t bh[4][4], bl[4][4];
#pragma unroll
            for (int np = 0; np < 4; np++) {
                uint32_t bo = (uint32_t)(np * 16 + ((lane >> 4) << 3) + (lane & 7)) * FROWB
                            + (uint32_t)(k16 * 16 + (((lane >> 3) & 1) << 3)) * 2;
                ldsm_x4(bh[np], st + 0 * FK_BYTES + bo);
                ldsm_x4(bl[np], st + 1 * FK_BYTES + bo);
            }
#pragma unroll
            for (int np = 0; np < 4; np++) {
                mma_bf16(sacc[2 * np + 0], qh[k16], bh[np] + 0);
                mma_bf16(sacc[2 * np + 1], qh[k16], bh[np] + 2);
            }
#pragma unroll
            for (int np = 0; np < 4; np++) {
                mma_bf16(sacc[2 * np + 0], qh[k16], bl[np] + 0);
                mma_bf16(sacc[2 * np + 1], qh[k16], bl[np] + 2);
            }
#pragma unroll
            for (int np = 0; np < 4; np++) {
                mma_bf16(sacc[2 * np + 0], ql[k16], bh[np] + 0);
                mma_bf16(sacc[2 * np + 1], ql[k16], bh[np] + 2);
            }
        }

        // ---- online softmax ----
#pragma unroll
        for (int rr = 0; rr < 2; rr++) {
            float mx = -1e30f;
#pragma unroll
            for (int nt = 0; nt < 8; nt++)
                mx = fmaxf(mx, fmaxf(sacc[nt][2 * rr], sacc[nt][2 * rr + 1]));
            mx = fmaxf(mx, __shfl_xor_sync(0xffffffffu, mx, 1));
            mx = fmaxf(mx, __shfl_xor_sync(0xffffffffu, mx, 2));
            float mn = fmaxf(m[rr], mx);
            float alpha = __expf(m[rr] - mn);
            m[rr] = mn;
            float su = 0.f;
#pragma unroll
            for (int nt = 0; nt < 8; nt++) {
                float p0 = __expf(sacc[nt][2 * rr] - mn);
                float p1 = __expf(sacc[nt][2 * rr + 1] - mn);
                sacc[nt][2 * rr] = p0;
                sacc[nt][2 * rr + 1] = p1;
                su += p0 + p1;
            }
            su += __shfl_xor_sync(0xffffffffu, su, 1);
            su += __shfl_xor_sync(0xffffffffu, su, 2);
            l[rr] = l[rr] * alpha + su;
#pragma unroll
            for (int nt = 0; nt < 8; nt++) {
                oacc[nt][2 * rr]     *= alpha;
                oacc[nt][2 * rr + 1] *= alpha;
            }
        }

        // ---- P -> A fragments (hi/lo), register-local ----
        uint32_t ph[4][4], pl[4][4];
#pragma unroll
        for (int j = 0; j < 4; j++) {
            split_pack(sacc[2 * j][0],     sacc[2 * j][1],     ph[j][0], pl[j][0]);
            split_pack(sacc[2 * j][2],     sacc[2 * j][3],     ph[j][1], pl[j][1]);
            split_pack(sacc[2 * j + 1][0], sacc[2 * j + 1][1], ph[j][2], pl[j][2]);
            split_pack(sacc[2 * j + 1][2], sacc[2 * j + 1][3], ph[j][3], pl[j][3]);
        }

        // ---- O += P V (3-term split) ----
#pragma unroll
        for (int j = 0; j < 4; j++) {
            uint32_t vh[4][4], vl[4][4];
#pragma unroll
            for (int np = 0; np < 4; np++) {
                uint32_t bo = (uint32_t)(np * 16 + ((lane >> 4) << 3) + (lane & 7)) * FROWB
                            + (uint32_t)(j * 16 + (((lane >> 3) & 1) << 3)) * 2;
                ldsm_x4(vh[np], st + 2 * FK_BYTES + bo);
                ldsm_x4(vl[np], st + 3 * FK_BYTES + bo);
            }
#pragma unroll
            for (int np = 0; np < 4; np++) {
                mma_bf16(oacc[2 * np + 0], ph[j], vh[np] + 0);
                mma_bf16(oacc[2 * np + 1], ph[j], vh[np] + 2);
            }
#pragma unroll
            for (int np = 0; np < 4; np++) {
                mma_bf16(oacc[2 * np + 0], ph[j], vl[np] + 0);
                mma_bf16(oacc[2 * np + 1], ph[j], vl[np] + 2);
            }
#pragma unroll
            for (int np = 0; np < 4; np++) {
                mma_bf16(oacc[2 * np + 0], pl[j], vh[np] + 0);
                mma_bf16(oacc[2 * np + 1], pl[j], vh[np] + 2);
            }
        }
        __syncthreads();
    }

    // ---- normalize + write ----
    float inv0 = 1.f / l[0], inv1 = 1.f / l[1];
    int rowg = b * SEQ + q0 + wid * 16 + g;
#pragma unroll
    for (int nt = 0; nt < 8; nt++) {
        int col = h * 64 + nt * 8 + 2 * tg;
        *(float2*)&Cp[(size_t)rowg * D_MODEL + col] =
            make_float2(oacc[nt][0] * inv0, oacc[nt][1] * inv0);
        *(float2*)&Cp[(size_t)(rowg + 8) * D_MODEL + col] =
            make_float2(oacc[nt][2] * inv1, oacc[nt][3] * inv1);
    }
}

// ---------------- launch --------------------------------------------------------
extern "C" void kernel_launch(void* const* d_in, const int* in_sizes, int n_in,
                              void* d_out, int out_size)
{
    const float* query = (const float*)d_in[0];
    const float* key   = (const float*)d_in[1];
    const float* value = (const float*)d_in[2];
    const float* Wq = (const float*)d_in[3];
    const float* bq = (const float*)d_in[4];
    const float* Wk = (const float*)d_in[5];
    const float* bk = (const float*)d_in[6];
    const float* Wv = (const float*)d_in[7];
    const float* bv = (const float*)d_in[8];
    const float* Wo = (const float*)d_in[9];
    const float* bo = (const float*)d_in[10];
    float* out = (float*)d_out;
    (void)in_sizes; (void)n_in; (void)out_size;

    float *gQ, *gK, *gV, *gC;
    __nv_bfloat16 *gAh, *gAl, *gBh, *gBl;
    __nv_bfloat16 *gQh, *gQl, *gKh, *gKl, *gVth, *gVtl;
    cudaGetSymbolAddress((void**)&gQ, g_Q);
    cudaGetSymbolAddress((void**)&gK, g_K);
    cudaGetSymbolAddress((void**)&gV, g_V);
    cudaGetSymbolAddress((void**)&gC, g_C);
    cudaGetSymbolAddress((void**)&gAh, g_Ah);
    cudaGetSymbolAddress((void**)&gAl, g_Al);
    cudaGetSymbolAddress((void**)&gBh, g_Bh);
    cudaGetSymbolAddress((void**)&gBl, g_Bl);
    cudaGetSymbolAddress((void**)&gQh, g_Qh);
    cudaGetSymbolAddress((void**)&gQl, g_Ql);
    cudaGetSymbolAddress((void**)&gKh, g_Kh);
    cudaGetSymbolAddress((void**)&gKl, g_Kl);
    cudaGetSymbolAddress((void**)&gVth, g_Vth);
    cudaGetSymbolAddress((void**)&gVtl, g_Vtl);

    const int n4 = M_TOT * D_MODEL / 4;
    const dim3 tgrid(D_MODEL / 32, D_MODEL / 32);
    const dim3 tblk(32, 8);
    const dim3 ggrid(D_MODEL / TBN, M_TOT / TBM);   // (8, 64)

    cudaFuncSetAttribute(gemm_bf16split,
                         cudaFuncAttributeMaxDynamicSharedMemorySize, GEMM_SMEM);
    cudaFuncSetAttribute(flash_hmma,
                         cudaFuncAttributeMaxDynamicSharedMemorySize, FLASH_SMEM);

    rope_table_kernel<<<(SEQ * 32 + 255) / 256, 256>>>();

    // Q projection
    split_bf16s<<<(n4 + 255) / 256, 256>>>((const float4*)query,
        (__nv_bfloat162*)gAh, (__nv_bfloat162*)gAl, n4, 1.f);
    splitT_bf16<<<tgrid, tblk>>>(Wq, gBh, gBl);
    gemm_bf16split<<<ggrid, 256, GEMM_SMEM>>>(gAh, gAl, gBh, gBl, bq, gQ);
    // K projection
    split_bf16s<<<(n4 + 255) / 256, 256>>>((const float4*)key,
        (__nv_bfloat162*)gAh, (__nv_bfloat162*)gAl, n4, 1.f);
    splitT_bf16<<<tgrid, tblk>>>(Wk, gBh, gBl);
    gemm_bf16split<<<ggrid, 256, GEMM_SMEM>>>(gAh, gAl, gBh, gBl, bk, gK);
    // V projection
    split_bf16s<<<(n4 + 255) / 256, 256>>>((const float4*)value,
        (__nv_bfloat162*)gAh, (__nv_bfloat162*)gAl, n4, 1.f);
    splitT_bf16<<<tgrid, tblk>>>(Wv, gBh, gBl);
    gemm_bf16split<<<ggrid, 256, GEMM_SMEM>>>(gAh, gAl, gBh, gBl, bv, gV);

    // fused RoPE + attention split for Q/K; V transpose-split
    int nrope = M_TOT * NUM_HEADS * (HEAD_DIM / 2);
    rope_split<<<(nrope + 255) / 256, 256>>>(gQ, gK, gQh, gQl, gKh, gKl);
    splitT_v<<<dim3(D_MODEL / 32, M_TOT / 32), tblk>>>(gV, gVth, gVtl);

    // attention
    flash_hmma<<<dim3(SEQ / 128, NUM_HEADS, BATCH), 256, FLASH_SMEM>>>(
        gQh, gQl, gKh, gKl, gVth, gVtl, gC);

    // output projection
    split_bf16s<<<(n4 + 255) / 256, 256>>>((const float4*)gC,
        (__nv_bfloat162*)gAh, (__nv_bfloat162*)gAl, n4, 1.f);
    splitT_bf16<<<tgrid, tblk>>>(Wo, gBh, gBl);
    gemm_bf16split<<<ggrid, 256, GEMM_SMEM>>>(gAh, gAl, gBh, gBl, bo, out);
}